// round 4
// baseline (speedup 1.0000x reference)
#include <cuda_runtime.h>
#include <stdint.h>

// Problem dims (fixed by the reference)
#define BB   2
#define SS   2048
#define MM   (BB * SS)   // 4096 rows
#define HH   512         // hidden
#define VV   32000       // vocab
#define KK   300         // top-k

// ---------------- scratch (device globals; no allocation allowed) -------
__device__ unsigned g_keys[(size_t)MM * VV];  // 524 MB: monotone keys of tanh(tanh(H@W_bin))
__device__ float    g_wt[(size_t)VV * HH];    // 65.5 MB: W_out transposed
__device__ int      g_topk[(size_t)MM * KK];  // selected indices, sorted

// ---------------- XLA/MLIR fast-tanh, FMA variant (BIT-EXACT — FROZEN) ---
// Verified round 3: reproduces the reference's tanh bits exactly.
__device__ __forceinline__ float xla_tanh(float v) {
    float ax = fabsf(v);
    float x  = fminf(fmaxf(v, -7.99881172180175781f), 7.99881172180175781f);
    float x2 = __fmul_rn(x, x);
    float p = __fmaf_rn(x2, -2.76076847742355e-16f, 2.00018790482477e-13f);
    p = __fmaf_rn(x2, p, -8.60467152213735e-11f);
    p = __fmaf_rn(x2, p,  5.12229709037114e-08f);
    p = __fmaf_rn(x2, p,  1.48572235717979e-05f);
    p = __fmaf_rn(x2, p,  6.37261928875436e-04f);
    p = __fmaf_rn(x2, p,  4.89352455891786e-03f);
    p = __fmul_rn(x, p);
    float q = __fmaf_rn(x2, 1.19825839466702e-06f, 1.18534705686654e-04f);
    q = __fmaf_rn(x2, q, 2.26843463243900e-03f);
    q = __fmaf_rn(x2, q, 4.89352518554385e-03f);
    float r = __fdiv_rn(p, q);
    return (ax < 0.0004f) ? v : r;
}

// monotone float -> uint transform (preserves total order, equal bits tie)
__device__ __forceinline__ unsigned fkey(float f) {
    unsigned u = __float_as_uint(f);
    return (u & 0x80000000u) ? ~u : (u | 0x80000000u);
}

// ---------------- W_out transpose: [H,V] -> [V,H] ------------------------
__global__ void transpose_kernel(const float* __restrict__ W) {
    __shared__ float tile[32][33];
    int x = blockIdx.x * 32 + threadIdx.x;  // vocab
    int y = blockIdx.y * 32 + threadIdx.y;  // hidden
#pragma unroll
    for (int i = 0; i < 32; i += 8)
        tile[threadIdx.y + i][threadIdx.x] = W[(size_t)(y + i) * VV + x];
    __syncthreads();
    int xo = blockIdx.y * 32 + threadIdx.x;  // hidden
    int yo = blockIdx.x * 32 + threadIdx.y;  // vocab
#pragma unroll
    for (int i = 0; i < 32; i += 8)
        g_wt[(size_t)(yo + i) * HH + xo] = tile[threadIdx.x][threadIdx.y + i];
}

// ---------------- fp32 SGEMM + double-tanh epilogue (BIT-EXACT — FROZEN) --
// Single-accumulator ASCENDING-k fp32 FMA chain per output element.
// DO NOT reorder / split K.
__global__ __launch_bounds__(256) void sgemm_kernel(
    const float* __restrict__ A,   // [MM, HH]
    const float* __restrict__ Bm)  // [HH, VV]
{
    __shared__ float As[8][128];
    __shared__ float Bs[8][128];

    const int bx = blockIdx.x;       // N tile
    const int by = blockIdx.y;       // M tile
    const int tid = threadIdx.x;
    const int tx = tid % 16;         // 16 cols of 8
    const int ty = tid / 16;         // 16 rows of 8

    const float* Ab = A + (size_t)by * 128 * HH;
    const float* Bb = Bm + (size_t)bx * 128;

    const int aRow = tid >> 1;          // 0..127
    const int aCol = (tid & 1) * 4;     // 0 or 4
    const int bRow = tid >> 5;          // 0..7
    const int bCol = (tid & 31) * 4;    // 0..124

    float acc[8][8];
#pragma unroll
    for (int i = 0; i < 8; i++)
#pragma unroll
        for (int j = 0; j < 8; j++) acc[i][j] = 0.f;

    for (int k0 = 0; k0 < HH; k0 += 8) {
        float4 av = *(const float4*)(Ab + (size_t)aRow * HH + k0 + aCol);
        As[aCol + 0][aRow] = av.x;
        As[aCol + 1][aRow] = av.y;
        As[aCol + 2][aRow] = av.z;
        As[aCol + 3][aRow] = av.w;
        float4 bv = *(const float4*)(Bb + (size_t)(k0 + bRow) * VV + bCol);
        *(float4*)&Bs[bRow][bCol] = bv;
        __syncthreads();
#pragma unroll
        for (int kk = 0; kk < 8; kk++) {
            float ar[8], br[8];
#pragma unroll
            for (int i = 0; i < 8; i++) ar[i] = As[kk][ty * 8 + i];
#pragma unroll
            for (int j = 0; j < 8; j++) br[j] = Bs[kk][tx * 8 + j];
#pragma unroll
            for (int i = 0; i < 8; i++)
#pragma unroll
                for (int j = 0; j < 8; j++) acc[i][j] = fmaf(ar[i], br[j], acc[i][j]);
        }
        __syncthreads();
    }

    unsigned* Cb = g_keys + (size_t)(by * 128 + ty * 8) * VV + (size_t)bx * 128 + tx * 8;
#pragma unroll
    for (int i = 0; i < 8; i++) {
        unsigned k[8];
#pragma unroll
        for (int j = 0; j < 8; j++)
            k[j] = fkey(xla_tanh(xla_tanh(acc[i][j])));
        *(uint4*)(Cb + (size_t)i * VV)     = make_uint4(k[0], k[1], k[2], k[3]);
        *(uint4*)(Cb + (size_t)i * VV + 4) = make_uint4(k[4], k[5], k[6], k[7]);
    }
}

// ---------------- exact top-300 per row (radix select + bitonic) ---------
__global__ __launch_bounds__(256) void topk_kernel() {
    const int row = blockIdx.x;
    const unsigned* s = g_keys + (size_t)row * VV;
    const int tid = threadIdx.x;

    __shared__ unsigned hist[256];
    __shared__ unsigned sh_prefix;
    __shared__ int sh_k;
    if (tid == 0) { sh_prefix = 0u; sh_k = KK; }
    __syncthreads();

    // MSB-first radix select: find the 300th-largest key P
    for (int pass = 3; pass >= 0; --pass) {
        hist[tid] = 0;
        __syncthreads();
        const unsigned prefix = sh_prefix;
        const unsigned mask_hi = (pass == 3) ? 0u : (0xFFFFFFFFu << ((pass + 1) * 8));
        const int shift = pass * 8;
        for (int i = tid; i < VV; i += 256) {
            unsigned u = s[i];
            if ((u & mask_hi) == prefix)
                atomicAdd(&hist[(u >> shift) & 0xFFu], 1u);
        }
        __syncthreads();
        if (tid == 0) {
            int k = sh_k;
            unsigned cum = 0;
            for (int b = 255; b >= 0; --b) {
                cum += hist[b];
                if ((int)cum >= k) {
                    sh_k = k - (int)(cum - hist[b]);
                    sh_prefix = prefix | ((unsigned)b << shift);
                    break;
                }
            }
        }
        __syncthreads();
    }
    const unsigned P = sh_prefix;
    const int kneed = sh_k;  // how many elements == P to take (smallest indices)

    __shared__ int n_gt, n_eq;
    __shared__ unsigned sel_key[KK];
    __shared__ int sel_idx[KK];
    __shared__ int eq_idx[128];
    if (tid == 0) { n_gt = 0; n_eq = 0; }
    __syncthreads();
    for (int i = tid; i < VV; i += 256) {
        unsigned u = s[i];
        if (u > P) {
            int p = atomicAdd(&n_gt, 1);
            sel_key[p] = u; sel_idx[p] = i;
        } else if (u == P) {
            int p = atomicAdd(&n_eq, 1);
            if (p < 128) eq_idx[p] = i;
        }
    }
    __syncthreads();
    if (tid == 0) {
        int ne = n_eq; if (ne > 128) ne = 128;
        for (int a = 1; a < ne; a++) {   // insertion sort ascending index
            int v = eq_idx[a]; int b = a - 1;
            while (b >= 0 && eq_idx[b] > v) { eq_idx[b + 1] = eq_idx[b]; --b; }
            eq_idx[b + 1] = v;
        }
        int base = n_gt;
        int take = kneed; if (take > ne) take = ne;
        for (int a = 0; a < take; a++) { sel_key[base + a] = P; sel_idx[base + a] = eq_idx[a]; }
    }
    __syncthreads();

    // Sort 300 selected: descending key, ascending index (matches lax.top_k)
    __shared__ unsigned long long skey[512];
    for (int i = tid; i < 512; i += 256)
        skey[i] = (i < KK)
            ? (((unsigned long long)sel_key[i] << 32) | (unsigned long long)(0xFFFFFFFFu - (unsigned)sel_idx[i]))
            : 0ull;
    __syncthreads();
    for (int ks = 2; ks <= 512; ks <<= 1) {
        for (int j = ks >> 1; j > 0; j >>= 1) {
            for (int i = tid; i < 512; i += 256) {
                int ixj = i ^ j;
                if (ixj > i) {
                    unsigned long long a = skey[i], b = skey[ixj];
                    bool up = ((i & ks) == 0);
                    bool sw = up ? (a < b) : (a > b);  // global descending
                    if (sw) { skey[i] = b; skey[ixj] = a; }
                }
            }
            __syncthreads();
        }
    }
    for (int i = tid; i < KK; i += 256) {
        unsigned low = (unsigned)(skey[i] & 0xFFFFFFFFu);
        g_topk[(size_t)row * KK + i] = (int)(0xFFFFFFFFu - low);
    }
}

// ---------------- gathered dot + scatter into sparse output --------------
// Output buffer is float32 throughout: indices are written as FLOAT values
// (exactly representable; harness compares the whole buffer as float32).
__global__ __launch_bounds__(256) void scatter_kernel(
    const float* __restrict__ hs, float* __restrict__ out_logits,
    float* __restrict__ out_idx)
{
    const int row = blockIdx.x;
    __shared__ float h[HH];
    const int tid = threadIdx.x;
    for (int i = tid; i < HH; i += 256) h[i] = hs[(size_t)row * HH + i];
    __syncthreads();

    const int warp = tid >> 5, lane = tid & 31;
    for (int c = warp; c < KK; c += 8) {
        int idx = g_topk[(size_t)row * KK + c];
        const float* w = g_wt + (size_t)idx * HH;
        float sum = 0.f;
#pragma unroll
        for (int t = lane; t < HH; t += 32) sum = fmaf(h[t], w[t], sum);
#pragma unroll
        for (int o = 16; o > 0; o >>= 1) sum += __shfl_down_sync(0xFFFFFFFFu, sum, o);
        if (lane == 0) {
            out_logits[(size_t)row * VV + idx] = sum;
            out_idx[(size_t)row * KK + c] = (float)idx;
        }
    }
}

// ---------------- launch --------------------------------------------------
extern "C" void kernel_launch(void* const* d_in, const int* in_sizes, int n_in,
                              void* d_out, int out_size) {
    const float* hs    = (const float*)d_in[0];  // [2,2048,512]
    const float* w_out = (const float*)d_in[1];  // [512,32000]
    const float* w_bin = (const float*)d_in[2];  // [512,32000]
    float* out = (float*)d_out;

    const size_t logitsN = (size_t)MM * VV;              // 131,072,000

    // zero the sparse logits region
    size_t zeroN = logitsN;
    if ((size_t)out_size < zeroN) zeroN = (size_t)out_size;
    cudaMemsetAsync(d_out, 0, zeroN * sizeof(float), 0);

    transpose_kernel<<<dim3(VV / 32, HH / 32), dim3(32, 8), 0, 0>>>(w_out);
    sgemm_kernel<<<dim3(VV / 128, MM / 128), 256, 0, 0>>>(hs, w_bin);
    topk_kernel<<<MM, 256, 0, 0>>>();
    scatter_kernel<<<MM, 256, 0, 0>>>(hs, out, out + logitsN);
}

// round 5
// speedup vs baseline: 1.1938x; 1.1938x over previous
#include <cuda_runtime.h>
#include <stdint.h>

typedef unsigned long long u64;

// Problem dims (fixed by the reference)
#define BB   2
#define SS   2048
#define MM   (BB * SS)   // 4096 rows
#define HH   512         // hidden
#define VV   32000       // vocab
#define KK   300         // top-k
#define CAP  2048        // candidate list capacity per row
#define T_CAND 0.7480f   // y-threshold (z ~ 2.08); boundary y ~0.754 (z~2.34)

// ---------------- scratch (device globals; no allocation allowed) -------
__device__ unsigned g_keys[(size_t)MM * VV];   // keys (fallback path only)
__device__ float    g_wt[(size_t)VV * HH];     // W_out transposed
__device__ int      g_topk[(size_t)MM * KK];   // selected indices, sorted
__device__ u64      g_cand[(size_t)MM * CAP];  // (key<<32 | ~idx) candidates
__device__ int      g_cnt[MM];                 // per-row candidate count

// ---------------- packed f32x2 helpers (bitwise == 2x scalar rn FMA) -----
__device__ __forceinline__ u64 pack2(float lo, float hi) {
    u64 r; asm("mov.b64 %0, {%1, %2};" : "=l"(r) : "f"(lo), "f"(hi)); return r;
}
__device__ __forceinline__ void unpack2(u64 v, float& lo, float& hi) {
    asm("mov.b64 {%0, %1}, %2;" : "=f"(lo), "=f"(hi) : "l"(v));
}
__device__ __forceinline__ void ffma2(u64& d, u64 a, u64 b) {
    asm("fma.rn.f32x2 %0, %1, %2, %0;" : "+l"(d) : "l"(a), "l"(b));
}

// ---------------- XLA/MLIR fast-tanh, FMA variant (BIT-EXACT — FROZEN) ---
__device__ __forceinline__ float xla_tanh(float v) {
    float ax = fabsf(v);
    float x  = fminf(fmaxf(v, -7.99881172180175781f), 7.99881172180175781f);
    float x2 = __fmul_rn(x, x);
    float p = __fmaf_rn(x2, -2.76076847742355e-16f, 2.00018790482477e-13f);
    p = __fmaf_rn(x2, p, -8.60467152213735e-11f);
    p = __fmaf_rn(x2, p,  5.12229709037114e-08f);
    p = __fmaf_rn(x2, p,  1.48572235717979e-05f);
    p = __fmaf_rn(x2, p,  6.37261928875436e-04f);
    p = __fmaf_rn(x2, p,  4.89352455891786e-03f);
    p = __fmul_rn(x, p);
    float q = __fmaf_rn(x2, 1.19825839466702e-06f, 1.18534705686654e-04f);
    q = __fmaf_rn(x2, q, 2.26843463243900e-03f);
    q = __fmaf_rn(x2, q, 4.89352518554385e-03f);
    float r = __fdiv_rn(p, q);
    return (ax < 0.0004f) ? v : r;
}

__device__ __forceinline__ unsigned fkey(float f) {
    unsigned u = __float_as_uint(f);
    return (u & 0x80000000u) ? ~u : (u | 0x80000000u);
}

// ---------------- W_out transpose: [H,V] -> [V,H] ------------------------
__global__ void transpose_kernel(const float* __restrict__ W) {
    __shared__ float tile[32][33];
    int x = blockIdx.x * 32 + threadIdx.x;
    int y = blockIdx.y * 32 + threadIdx.y;
#pragma unroll
    for (int i = 0; i < 32; i += 8)
        tile[threadIdx.y + i][threadIdx.x] = W[(size_t)(y + i) * VV + x];
    __syncthreads();
    int xo = blockIdx.y * 32 + threadIdx.x;
    int yo = blockIdx.x * 32 + threadIdx.y;
#pragma unroll
    for (int i = 0; i < 32; i += 8)
        g_wt[(size_t)(yo + i) * HH + xo] = tile[threadIdx.x][threadIdx.y + i];
}

// ---------------- fp32 SGEMM (f32x2 packed) + double-tanh epilogue -------
// Per-element accumulation remains a single ASCENDING-k rn-FMA chain
// (f32x2 = two independent IEEE rn FMAs) — bitwise identical to round 4.
__global__ __launch_bounds__(256) void sgemm_kernel(
    const float* __restrict__ A,   // [MM, HH]
    const float* __restrict__ Bm)  // [HH, VV]
{
    __shared__ float As[8][128];
    __shared__ float Bs[8][128];

    const int bx = blockIdx.x;       // N tile
    const int by = blockIdx.y;       // M tile
    const int tid = threadIdx.x;
    const int tx = tid % 16;
    const int ty = tid / 16;

    const float* Ab = A + (size_t)by * 128 * HH;
    const float* Bb = Bm + (size_t)bx * 128;

    const int aRow = tid >> 1;
    const int aCol = (tid & 1) * 4;
    const int bRow = tid >> 5;
    const int bCol = (tid & 31) * 4;

    u64 acc2[8][4];
#pragma unroll
    for (int i = 0; i < 8; i++)
#pragma unroll
        for (int j = 0; j < 4; j++) acc2[i][j] = 0ull;

    // prefetch first tile
    float4 av = *(const float4*)(Ab + (size_t)aRow * HH + aCol);
    float4 bv = *(const float4*)(Bb + (size_t)bRow * VV + bCol);

    for (int k0 = 0; k0 < HH; k0 += 8) {
        As[aCol + 0][aRow] = av.x;
        As[aCol + 1][aRow] = av.y;
        As[aCol + 2][aRow] = av.z;
        As[aCol + 3][aRow] = av.w;
        *(float4*)&Bs[bRow][bCol] = bv;
        __syncthreads();

        if (k0 + 8 < HH) {
            av = *(const float4*)(Ab + (size_t)aRow * HH + (k0 + 8) + aCol);
            bv = *(const float4*)(Bb + (size_t)(k0 + 8 + bRow) * VV + bCol);
        }

#pragma unroll
        for (int kk = 0; kk < 8; kk++) {
            float4 a0 = *(const float4*)&As[kk][ty * 8];
            float4 a1 = *(const float4*)&As[kk][ty * 8 + 4];
            float4 b0 = *(const float4*)&Bs[kk][tx * 8];
            float4 b1 = *(const float4*)&Bs[kk][tx * 8 + 4];
            u64 bp0 = pack2(b0.x, b0.y);
            u64 bp1 = pack2(b0.z, b0.w);
            u64 bp2 = pack2(b1.x, b1.y);
            u64 bp3 = pack2(b1.z, b1.w);
            float ar[8] = {a0.x, a0.y, a0.z, a0.w, a1.x, a1.y, a1.z, a1.w};
#pragma unroll
            for (int i = 0; i < 8; i++) {
                u64 ap = pack2(ar[i], ar[i]);
                ffma2(acc2[i][0], ap, bp0);
                ffma2(acc2[i][1], ap, bp1);
                ffma2(acc2[i][2], ap, bp2);
                ffma2(acc2[i][3], ap, bp3);
            }
        }
        __syncthreads();
    }

    // epilogue: double-tanh, key, write keys + append candidates
    const int row0 = by * 128 + ty * 8;
    const int col0 = bx * 128 + tx * 8;
    unsigned* Cb = g_keys + (size_t)row0 * VV + col0;
#pragma unroll
    for (int i = 0; i < 8; i++) {
        const int row = row0 + i;
        float vals[8];
#pragma unroll
        for (int j4 = 0; j4 < 4; j4++) unpack2(acc2[i][j4], vals[j4 * 2], vals[j4 * 2 + 1]);
        unsigned k[8];
#pragma unroll
        for (int j = 0; j < 8; j++) {
            float y = xla_tanh(xla_tanh(vals[j]));
            k[j] = fkey(y);
            if (y >= T_CAND) {
                int pos = atomicAdd(&g_cnt[row], 1);
                if (pos < CAP)
                    g_cand[(size_t)row * CAP + pos] =
                        ((u64)k[j] << 32) | (u64)(0xFFFFFFFFu - (unsigned)(col0 + j));
            }
        }
        *(uint4*)(Cb + (size_t)i * VV)     = make_uint4(k[0], k[1], k[2], k[3]);
        *(uint4*)(Cb + (size_t)i * VV + 4) = make_uint4(k[4], k[5], k[6], k[7]);
    }
}

// ---------------- top-300: candidate sort (fast) or radix fallback -------
__global__ __launch_bounds__(256) void topk_kernel() {
    const int row = blockIdx.x;
    const int tid = threadIdx.x;

    __shared__ u64 skey[CAP];            // 16 KB
    __shared__ unsigned hist[256];
    __shared__ unsigned sh_prefix;
    __shared__ int sh_k, n_gt, n_eq, sh_n;
    __shared__ int eq_idx[128];

    const int cnt = g_cnt[row];

    if (cnt >= KK && cnt <= CAP) {
        // ---- fast path: sort the candidate list ----
        int n = 512;
        while (n < cnt) n <<= 1;
        const u64* src = g_cand + (size_t)row * CAP;
        for (int i = tid; i < n; i += 256) skey[i] = (i < cnt) ? src[i] : 0ull;
        if (tid == 0) sh_n = n;
        __syncthreads();
    } else {
        // ---- fallback: radix select over the full key row ----
        const unsigned* s = g_keys + (size_t)row * VV;
        if (tid == 0) { sh_prefix = 0u; sh_k = KK; }
        __syncthreads();
        for (int pass = 3; pass >= 0; --pass) {
            hist[tid] = 0;
            __syncthreads();
            const unsigned prefix = sh_prefix;
            const unsigned mask_hi = (pass == 3) ? 0u : (0xFFFFFFFFu << ((pass + 1) * 8));
            const int shift = pass * 8;
            for (int i = tid; i < VV; i += 256) {
                unsigned u = s[i];
                if ((u & mask_hi) == prefix)
                    atomicAdd(&hist[(u >> shift) & 0xFFu], 1u);
            }
            __syncthreads();
            if (tid == 0) {
                int k = sh_k;
                unsigned cum = 0;
                for (int b = 255; b >= 0; --b) {
                    cum += hist[b];
                    if ((int)cum >= k) {
                        sh_k = k - (int)(cum - hist[b]);
                        sh_prefix = prefix | ((unsigned)b << shift);
                        break;
                    }
                }
            }
            __syncthreads();
        }
        const unsigned P = sh_prefix;
        const int kneed = sh_k;
        if (tid == 0) { n_gt = 0; n_eq = 0; }
        __syncthreads();
        for (int i = tid; i < VV; i += 256) {
            unsigned u = s[i];
            if (u > P) {
                int p = atomicAdd(&n_gt, 1);
                skey[p] = ((u64)u << 32) | (u64)(0xFFFFFFFFu - (unsigned)i);
            } else if (u == P) {
                int p = atomicAdd(&n_eq, 1);
                if (p < 128) eq_idx[p] = i;
            }
        }
        __syncthreads();
        if (tid == 0) {
            int ne = n_eq; if (ne > 128) ne = 128;
            for (int a = 1; a < ne; a++) {
                int v = eq_idx[a]; int b = a - 1;
                while (b >= 0 && eq_idx[b] > v) { eq_idx[b + 1] = eq_idx[b]; --b; }
                eq_idx[b + 1] = v;
            }
            int base = n_gt;
            int take = kneed; if (take > ne) take = ne;
            for (int a = 0; a < take; a++)
                skey[base + a] = ((u64)P << 32) | (u64)(0xFFFFFFFFu - (unsigned)eq_idx[a]);
            sh_n = 512;
        }
        __syncthreads();
        for (int i = tid; i < 512; i += 256)
            if (i >= n_gt + ((kneed < (n_eq > 128 ? 128 : n_eq)) ? kneed : (n_eq > 128 ? 128 : n_eq)))
                skey[i] = skey[i];  // keep
        // pad remainder
        for (int i = tid; i < 512; i += 256) {
            int filled = n_gt + ((kneed < n_eq) ? kneed : n_eq);
            if (filled > KK) filled = KK;
            if (i >= filled && i >= KK) skey[i] = 0ull;
        }
        __syncthreads();
        // ensure slots [KK,512) padded (n_gt+take == KK by construction)
        for (int i = tid; i < 512; i += 256) if (i >= KK) skey[i] = 0ull;
        __syncthreads();
    }

    // ---- bitonic sort: descending key, ascending index ----
    const int n = sh_n;
    for (int ks = 2; ks <= n; ks <<= 1) {
        for (int j = ks >> 1; j > 0; j >>= 1) {
            for (int i = tid; i < n; i += 256) {
                int ixj = i ^ j;
                if (ixj > i) {
                    u64 a = skey[i], b = skey[ixj];
                    bool up = ((i & ks) == 0);
                    bool sw = up ? (a < b) : (a > b);
                    if (sw) { skey[i] = b; skey[ixj] = a; }
                }
            }
            __syncthreads();
        }
    }
    for (int i = tid; i < KK; i += 256) {
        unsigned low = (unsigned)(skey[i] & 0xFFFFFFFFu);
        g_topk[(size_t)row * KK + i] = (int)(0xFFFFFFFFu - low);
    }
}

// ---------------- gathered dot + scatter into sparse output --------------
__global__ __launch_bounds__(256) void scatter_kernel(
    const float* __restrict__ hs, float* __restrict__ out_logits,
    float* __restrict__ out_idx)
{
    const int row = blockIdx.x;
    __shared__ float4 h4[HH / 4];
    const int tid = threadIdx.x;
    for (int i = tid; i < HH / 4; i += 256)
        h4[i] = ((const float4*)(hs + (size_t)row * HH))[i];
    __syncthreads();

    const int warp = tid >> 5, lane = tid & 31;
    for (int c = warp; c < KK; c += 8) {
        int idx = g_topk[(size_t)row * KK + c];
        const float4* w4 = (const float4*)(g_wt + (size_t)idx * HH);
        float sum = 0.f;
#pragma unroll
        for (int t = lane; t < HH / 4; t += 32) {
            float4 a = h4[t], b = w4[t];
            sum = fmaf(a.x, b.x, sum);
            sum = fmaf(a.y, b.y, sum);
            sum = fmaf(a.z, b.z, sum);
            sum = fmaf(a.w, b.w, sum);
        }
#pragma unroll
        for (int o = 16; o > 0; o >>= 1) sum += __shfl_down_sync(0xFFFFFFFFu, sum, o);
        if (lane == 0) {
            out_logits[(size_t)row * VV + idx] = sum;
            out_idx[(size_t)row * KK + c] = (float)idx;
        }
    }
}

// ---------------- launch --------------------------------------------------
extern "C" void kernel_launch(void* const* d_in, const int* in_sizes, int n_in,
                              void* d_out, int out_size) {
    const float* hs    = (const float*)d_in[0];  // [2,2048,512]
    const float* w_out = (const float*)d_in[1];  // [512,32000]
    const float* w_bin = (const float*)d_in[2];  // [512,32000]
    float* out = (float*)d_out;

    const size_t logitsN = (size_t)MM * VV;

    size_t zeroN = logitsN;
    if ((size_t)out_size < zeroN) zeroN = (size_t)out_size;
    cudaMemsetAsync(d_out, 0, zeroN * sizeof(float), 0);

    void* cnt_ptr = nullptr;
    cudaGetSymbolAddress(&cnt_ptr, g_cnt);
    cudaMemsetAsync(cnt_ptr, 0, MM * sizeof(int), 0);

    transpose_kernel<<<dim3(VV / 32, HH / 32), dim3(32, 8), 0, 0>>>(w_out);
    sgemm_kernel<<<dim3(VV / 128, MM / 128), 256, 0, 0>>>(hs, w_bin);
    topk_kernel<<<MM, 256, 0, 0>>>();
    scatter_kernel<<<MM, 256, 0, 0>>>(hs, out, out + logitsN);
}